// round 3
// baseline (speedup 1.0000x reference)
#include <cuda_runtime.h>
#include <cstdint>

// PARCOR -> LPC (Levinson step-up), rows x 25 f32.
// Persistent CTAs, 3-buffer ring: bulk-async load (tile i+1) || compute (tile i)
// || bulk-async store (tile i-1). Memory-bound; goal = saturate HBM.

#define ORDER 25
#define RPB   256                      // rows per tile, one thread per row
#define TILE_FLOATS (RPB * ORDER)      // 6400
#define TILE_BYTES  (TILE_FLOATS * 4)  // 25600 (16B-multiple)
#define NBUF  3
#define SMEM_DYN (NBUF * TILE_BYTES)   // 76800 B -> 2 CTAs/SM

__device__ __forceinline__ uint32_t smem_u32(const void* p) {
    uint32_t a;
    asm volatile("{ .reg .u64 x; cvta.to.shared.u64 x, %1; cvt.u32.u64 %0, x; }"
                 : "=r"(a) : "l"(p));
    return a;
}

__device__ __forceinline__ void mbar_wait(uint32_t mb, int parity) {
    uint32_t done;
    asm volatile(
        "{\n\t.reg .pred p;\n\t"
        "mbarrier.try_wait.parity.acquire.cta.shared::cta.b64 p, [%1], %2;\n\t"
        "selp.b32 %0, 1, 0, p;\n\t}"
        : "=r"(done) : "r"(mb), "r"((uint32_t)parity) : "memory");
    if (!done) {
        asm volatile(
            "{\n\t.reg .pred P1;\n\t"
            "WL_%=:\n\t"
            "mbarrier.try_wait.parity.acquire.cta.shared::cta.b64 P1, [%0], %1, 0x989680;\n\t"
            "@P1 bra.uni WD_%=;\n\t"
            "bra.uni WL_%=;\n\t"
            "WD_%=:\n\t}"
            :: "r"(mb), "r"((uint32_t)parity) : "memory");
    }
}

__global__ __launch_bounds__(RPB, 2)
void parcor_to_lpc_persist(const float* __restrict__ in, float* __restrict__ out,
                           int ntiles)
{
    extern __shared__ __align__(128) float buf[];   // NBUF * TILE_FLOATS
    __shared__ __align__(8) unsigned long long mbar[NBUF];

    const int t = threadIdx.x;
    const int c = blockIdx.x;
    const int G = gridDim.x;

    const uint32_t buf_a  = smem_u32(buf);
    const uint32_t mbar_a = smem_u32(mbar);

    if (t < NBUF) {
        asm volatile("mbarrier.init.shared.b64 [%0], 1;"
                     :: "r"(mbar_a + t * 8) : "memory");
    }
    __syncthreads();

    const int cnt = (ntiles > c) ? (ntiles - c + G - 1) / G : 0;
    if (cnt == 0) return;

    // prologue: kick off load of first tile into buf 0
    if (t == 0) {
        const float* g0 = in + (size_t)c * TILE_FLOATS;
        asm volatile("mbarrier.arrive.expect_tx.shared.b64 _, [%0], %1;"
                     :: "r"(mbar_a), "r"((uint32_t)TILE_BYTES) : "memory");
        asm volatile("cp.async.bulk.shared::cta.global.mbarrier::complete_tx::bytes "
                     "[%0], [%1], %2, [%3];"
                     :: "r"(buf_a), "l"(g0), "r"((uint32_t)TILE_BYTES), "r"(mbar_a)
                     : "memory");
    }

    for (int it = 0; it < cnt; ++it) {
        const int r = it % NBUF;
        const uint32_t ba = buf_a + r * TILE_BYTES;
        const uint32_t mb = mbar_a + r * 8;

        // thread0: reclaim the next ring slot (store it-2 done) and prefetch it+1
        if (t == 0) {
            asm volatile("cp.async.bulk.wait_group 1;" ::: "memory");
            if (it + 1 < cnt) {
                const int rn = (it + 1) % NBUF;
                const float* gn = in + ((size_t)c + (size_t)(it + 1) * G) * TILE_FLOATS;
                asm volatile("mbarrier.arrive.expect_tx.shared.b64 _, [%0], %1;"
                             :: "r"(mbar_a + rn * 8), "r"((uint32_t)TILE_BYTES) : "memory");
                asm volatile("cp.async.bulk.shared::cta.global.mbarrier::complete_tx::bytes "
                             "[%0], [%1], %2, [%3];"
                             :: "r"(buf_a + rn * TILE_BYTES), "l"(gn),
                                "r"((uint32_t)TILE_BYTES), "r"(mbar_a + rn * 8)
                             : "memory");
            }
        }

        // wait current tile's data
        mbar_wait(mb, (it / NBUF) & 1);

        // row -> registers (stride-25 words: gcd(25,32)=1, conflict-free)
        float* bp = buf + r * TILE_FLOATS + t * ORDER;
        float a[ORDER];
        #pragma unroll
        for (int i = 0; i < ORDER; ++i) a[i] = bp[i];

        // Levinson step-up, fully unrolled. a[m]==k[m] when step m runs.
        #pragma unroll
        for (int m = 2; m < ORDER; ++m) {
            const float km = a[m];
            #pragma unroll
            for (int j = 1; 2 * j < m; ++j) {
                const float tj = a[j];
                const float tk = a[m - j];
                a[j]     = fmaf(km, tk, tj);
                a[m - j] = fmaf(km, tj, tk);
            }
            if ((m & 1) == 0) {
                const int j = m >> 1;
                a[j] = fmaf(km, a[j], a[j]);
            }
        }

        // results into own smem slots, then bulk store
        #pragma unroll
        for (int i = 0; i < ORDER; ++i) bp[i] = a[i];
        __syncthreads();

        if (t == 0) {
            float* gd = out + ((size_t)c + (size_t)it * G) * TILE_FLOATS;
            asm volatile("fence.proxy.async;" ::: "memory");
            asm volatile("cp.async.bulk.global.shared::cta.bulk_group [%0], [%1], %2;"
                         :: "l"(gd), "r"(ba), "r"((uint32_t)TILE_BYTES) : "memory");
            asm volatile("cp.async.bulk.commit_group;" ::: "memory");
        }
    }

    if (t == 0) {
        asm volatile("cp.async.bulk.wait_group 0;" ::: "memory");
    }
}

// Fallback for row counts not divisible by RPB (not hit by the bench shape).
__global__ void parcor_to_lpc_scalar(const float* __restrict__ in,
                                     float* __restrict__ out, int rows)
{
    int r = blockIdx.x * blockDim.x + threadIdx.x;
    if (r >= rows) return;
    float a[ORDER];
    #pragma unroll
    for (int i = 0; i < ORDER; ++i) a[i] = in[(size_t)r * ORDER + i];
    #pragma unroll
    for (int m = 2; m < ORDER; ++m) {
        const float km = a[m];
        #pragma unroll
        for (int j = 1; 2 * j < m; ++j) {
            const float tj = a[j];
            const float tk = a[m - j];
            a[j]     = fmaf(km, tk, tj);
            a[m - j] = fmaf(km, tj, tk);
        }
        if ((m & 1) == 0) { const int j = m >> 1; a[j] = fmaf(km, a[j], a[j]); }
    }
    #pragma unroll
    for (int i = 0; i < ORDER; ++i) out[(size_t)r * ORDER + i] = a[i];
}

extern "C" void kernel_launch(void* const* d_in, const int* in_sizes, int n_in,
                              void* d_out, int out_size)
{
    const float* k = (const float*)d_in[0];
    float* out = (float*)d_out;

    const int total_elems = in_sizes[0];
    const int rows = total_elems / ORDER;

    if (rows % RPB == 0) {
        const int ntiles = rows / RPB;
        int dev = 0, nsm = 148;
        cudaGetDevice(&dev);
        cudaDeviceGetAttribute(&nsm, cudaDevAttrMultiProcessorCount, dev);
        int grid = 2 * nsm;
        if (grid > ntiles) grid = ntiles;

        cudaFuncSetAttribute(parcor_to_lpc_persist,
                             cudaFuncAttributeMaxDynamicSharedMemorySize, SMEM_DYN);
        parcor_to_lpc_persist<<<grid, RPB, SMEM_DYN>>>(k, out, ntiles);
    } else {
        parcor_to_lpc_scalar<<<(rows + RPB - 1) / RPB, RPB>>>(k, out, rows);
    }
}

// round 4
// speedup vs baseline: 1.2466x; 1.2466x over previous
#include <cuda_runtime.h>
#include <cstdint>

// PARCOR -> LPC (Levinson step-up), rows x 25 f32. HBM-bound.
// One-shot CTAs, bulk-async (UBLKCP) tile in / tile out, max occupancy:
// 128 rows/CTA (12.8 KB smem), 16 CTAs/SM, 64 warps/SM.

#define ORDER 25
#define RPB   128                      // rows per tile, one thread per row
#define TILE_FLOATS (RPB * ORDER)      // 3200
#define TILE_BYTES  (TILE_FLOATS * 4)  // 12800 (16B-multiple)

__device__ __forceinline__ uint32_t smem_u32(const void* p) {
    uint32_t a;
    asm volatile("{ .reg .u64 x; cvta.to.shared.u64 x, %1; cvt.u32.u64 %0, x; }"
                 : "=r"(a) : "l"(p));
    return a;
}

__global__ __launch_bounds__(RPB, 16)
void parcor_to_lpc_bulk(const float* __restrict__ in, float* __restrict__ out)
{
    extern __shared__ __align__(128) float buf[];   // TILE_FLOATS
    __shared__ __align__(8) unsigned long long mbar;

    const int t = threadIdx.x;
    const uint32_t buf_a  = smem_u32(buf);
    const uint32_t mbar_a = smem_u32(&mbar);

    const float* gsrc = in  + (size_t)blockIdx.x * TILE_FLOATS;
    float*       gdst = out + (size_t)blockIdx.x * TILE_FLOATS;

    if (t == 0) {
        asm volatile("mbarrier.init.shared.b64 [%0], 1;" :: "r"(mbar_a) : "memory");
    }
    __syncthreads();
    if (t == 0) {
        asm volatile("mbarrier.arrive.expect_tx.shared.b64 _, [%0], %1;"
                     :: "r"(mbar_a), "r"((uint32_t)TILE_BYTES) : "memory");
        asm volatile("cp.async.bulk.shared::cta.global.mbarrier::complete_tx::bytes "
                     "[%0], [%1], %2, [%3];"
                     :: "r"(buf_a), "l"(gsrc), "r"((uint32_t)TILE_BYTES), "r"(mbar_a)
                     : "memory");
    }

    // wait for tile arrival (acquire orders subsequent LDS)
    {
        uint32_t done;
        asm volatile(
            "{\n\t.reg .pred p;\n\t"
            "mbarrier.try_wait.parity.acquire.cta.shared::cta.b64 p, [%1], 0;\n\t"
            "selp.b32 %0, 1, 0, p;\n\t}"
            : "=r"(done) : "r"(mbar_a) : "memory");
        if (!done) {
            asm volatile(
                "{\n\t.reg .pred P1;\n\t"
                "WL_%=:\n\t"
                "mbarrier.try_wait.parity.acquire.cta.shared::cta.b64 P1, [%0], 0, 0x989680;\n\t"
                "@P1 bra.uni WD_%=;\n\t"
                "bra.uni WL_%=;\n\t"
                "WD_%=:\n\t}"
                :: "r"(mbar_a) : "memory");
        }
    }

    // row -> registers (stride-25 word reads: gcd(25,32)=1, conflict-free)
    float a[ORDER];
    float* bp = buf + t * ORDER;
    #pragma unroll
    for (int i = 0; i < ORDER; ++i) a[i] = bp[i];

    // Levinson step-up, fully unrolled. a[m]==k[m] when step m runs
    // (index m is first modified at step m+1).
    #pragma unroll
    for (int m = 2; m < ORDER; ++m) {
        const float km = a[m];
        #pragma unroll
        for (int j = 1; 2 * j < m; ++j) {
            const float tj = a[j];
            const float tk = a[m - j];
            a[j]     = fmaf(km, tk, tj);
            a[m - j] = fmaf(km, tj, tk);
        }
        if ((m & 1) == 0) {
            const int j = m >> 1;
            a[j] = fmaf(km, a[j], a[j]);
        }
    }

    // write back to OWN slots, then single bulk S->G store
    #pragma unroll
    for (int i = 0; i < ORDER; ++i) bp[i] = a[i];
    __syncthreads();

    if (t == 0) {
        asm volatile("fence.proxy.async;" ::: "memory");
        asm volatile("cp.async.bulk.global.shared::cta.bulk_group [%0], [%1], %2;"
                     :: "l"(gdst), "r"(buf_a), "r"((uint32_t)TILE_BYTES) : "memory");
        asm volatile("cp.async.bulk.commit_group;" ::: "memory");
        // wait until smem has been fully READ by the bulk engine before CTA
        // exit can release the allocation; .read is sufficient and cheaper.
        asm volatile("cp.async.bulk.wait_group.read 0;" ::: "memory");
    }
}

// Fallback for row counts not divisible by RPB (not hit by the bench shape).
__global__ void parcor_to_lpc_scalar(const float* __restrict__ in,
                                     float* __restrict__ out, int rows)
{
    int r = blockIdx.x * blockDim.x + threadIdx.x;
    if (r >= rows) return;
    float a[ORDER];
    #pragma unroll
    for (int i = 0; i < ORDER; ++i) a[i] = in[(size_t)r * ORDER + i];
    #pragma unroll
    for (int m = 2; m < ORDER; ++m) {
        const float km = a[m];
        #pragma unroll
        for (int j = 1; 2 * j < m; ++j) {
            const float tj = a[j];
            const float tk = a[m - j];
            a[j]     = fmaf(km, tk, tj);
            a[m - j] = fmaf(km, tj, tk);
        }
        if ((m & 1) == 0) { const int j = m >> 1; a[j] = fmaf(km, a[j], a[j]); }
    }
    #pragma unroll
    for (int i = 0; i < ORDER; ++i) out[(size_t)r * ORDER + i] = a[i];
}

extern "C" void kernel_launch(void* const* d_in, const int* in_sizes, int n_in,
                              void* d_out, int out_size)
{
    const float* k = (const float*)d_in[0];
    float* out = (float*)d_out;

    const int total_elems = in_sizes[0];
    const int rows = total_elems / ORDER;

    if (rows % RPB == 0) {
        cudaFuncSetAttribute(parcor_to_lpc_bulk,
                             cudaFuncAttributeMaxDynamicSharedMemorySize, TILE_BYTES);
        parcor_to_lpc_bulk<<<rows / RPB, RPB, TILE_BYTES>>>(k, out);
    } else {
        parcor_to_lpc_scalar<<<(rows + 255) / 256, 256>>>(k, out, rows);
    }
}

// round 5
// speedup vs baseline: 1.2521x; 1.0044x over previous
#include <cuda_runtime.h>
#include <cstdint>

// PARCOR -> LPC (Levinson step-up), rows x 25 f32. HBM-bound.
// CTA-level bulk-async load (25.6 KB, one TMA op), per-WARP bulk-async stores
// (3200 B each, no CTA-level store barrier). 256 thr, 8 CTAs/SM.

#define ORDER 25
#define RPB   256                       // rows per tile, one thread per row
#define TILE_FLOATS (RPB * ORDER)       // 6400
#define TILE_BYTES  (TILE_FLOATS * 4)   // 25600
#define WARP_FLOATS (32 * ORDER)        // 800
#define WARP_BYTES  (WARP_FLOATS * 4)   // 3200 (16B-multiple)

__device__ __forceinline__ uint32_t smem_u32(const void* p) {
    uint32_t a;
    asm volatile("{ .reg .u64 x; cvta.to.shared.u64 x, %1; cvt.u32.u64 %0, x; }"
                 : "=r"(a) : "l"(p));
    return a;
}

__global__ __launch_bounds__(RPB, 8)
void parcor_to_lpc_bulk(const float* __restrict__ in, float* __restrict__ out)
{
    extern __shared__ __align__(128) float buf[];   // TILE_FLOATS
    __shared__ __align__(8) unsigned long long mbar;

    const int t = threadIdx.x;
    const int w = t >> 5;
    const uint32_t buf_a  = smem_u32(buf);
    const uint32_t mbar_a = smem_u32(&mbar);

    const float* gsrc = in  + (size_t)blockIdx.x * TILE_FLOATS;
    float*       gdst = out + (size_t)blockIdx.x * TILE_FLOATS;

    // ---- one bulk G->S load for the whole tile ----
    if (t == 0) {
        asm volatile("mbarrier.init.shared.b64 [%0], 1;" :: "r"(mbar_a) : "memory");
        // fence: make the init visible to the async proxy before the TMA targets it
        asm volatile("fence.proxy.async.shared::cta;" ::: "memory");
        asm volatile("mbarrier.arrive.expect_tx.shared.b64 _, [%0], %1;"
                     :: "r"(mbar_a), "r"((uint32_t)TILE_BYTES) : "memory");
        asm volatile("cp.async.bulk.shared::cta.global.mbarrier::complete_tx::bytes "
                     "[%0], [%1], %2, [%3];"
                     :: "r"(buf_a), "l"(gsrc), "r"((uint32_t)TILE_BYTES), "r"(mbar_a)
                     : "memory");
    }
    __syncthreads();   // mbar init visible to all waiters

    // ---- all threads wait for tile arrival ----
    {
        uint32_t done;
        asm volatile(
            "{\n\t.reg .pred p;\n\t"
            "mbarrier.try_wait.parity.acquire.cta.shared::cta.b64 p, [%1], 0;\n\t"
            "selp.b32 %0, 1, 0, p;\n\t}"
            : "=r"(done) : "r"(mbar_a) : "memory");
        if (!done) {
            asm volatile(
                "{\n\t.reg .pred P1;\n\t"
                "WL_%=:\n\t"
                "mbarrier.try_wait.parity.acquire.cta.shared::cta.b64 P1, [%0], 0, 0x989680;\n\t"
                "@P1 bra.uni WD_%=;\n\t"
                "bra.uni WL_%=;\n\t"
                "WD_%=:\n\t}"
                :: "r"(mbar_a) : "memory");
        }
    }

    // ---- row -> registers (stride-25 words: gcd(25,32)=1, conflict-free) ----
    float a[ORDER];
    float* bp = buf + t * ORDER;
    #pragma unroll
    for (int i = 0; i < ORDER; ++i) a[i] = bp[i];

    // ---- Levinson step-up, fully unrolled; a[m]==k[m] when step m runs ----
    #pragma unroll
    for (int m = 2; m < ORDER; ++m) {
        const float km = a[m];
        #pragma unroll
        for (int j = 1; 2 * j < m; ++j) {
            const float tj = a[j];
            const float tk = a[m - j];
            a[j]     = fmaf(km, tk, tj);
            a[m - j] = fmaf(km, tj, tk);
        }
        if ((m & 1) == 0) {
            const int j = m >> 1;
            a[j] = fmaf(km, a[j], a[j]);
        }
    }

    // ---- write back to OWN slots ----
    #pragma unroll
    for (int i = 0; i < ORDER; ++i) bp[i] = a[i];

    // ---- per-warp bulk store: warp's 3200B smem region is written only by
    //      its own lanes, so __syncwarp suffices; no CTA barrier. ----
    __syncwarp();
    if ((t & 31) == 0) {
        asm volatile("fence.proxy.async.shared::cta;" ::: "memory");
        asm volatile("cp.async.bulk.global.shared::cta.bulk_group [%0], [%1], %2;"
                     :: "l"(gdst + w * WARP_FLOATS),
                        "r"(buf_a + (uint32_t)(w * WARP_BYTES)),
                        "r"((uint32_t)WARP_BYTES) : "memory");
        asm volatile("cp.async.bulk.commit_group;" ::: "memory");
        // smem must be fully read by the bulk engine before the CTA may exit
        asm volatile("cp.async.bulk.wait_group.read 0;" ::: "memory");
    }
}

// Fallback for row counts not divisible by RPB (not hit by the bench shape).
__global__ void parcor_to_lpc_scalar(const float* __restrict__ in,
                                     float* __restrict__ out, int rows)
{
    int r = blockIdx.x * blockDim.x + threadIdx.x;
    if (r >= rows) return;
    float a[ORDER];
    #pragma unroll
    for (int i = 0; i < ORDER; ++i) a[i] = in[(size_t)r * ORDER + i];
    #pragma unroll
    for (int m = 2; m < ORDER; ++m) {
        const float km = a[m];
        #pragma unroll
        for (int j = 1; 2 * j < m; ++j) {
            const float tj = a[j];
            const float tk = a[m - j];
            a[j]     = fmaf(km, tk, tj);
            a[m - j] = fmaf(km, tj, tk);
        }
        if ((m & 1) == 0) { const int j = m >> 1; a[j] = fmaf(km, a[j], a[j]); }
    }
    #pragma unroll
    for (int i = 0; i < ORDER; ++i) out[(size_t)r * ORDER + i] = a[i];
}

extern "C" void kernel_launch(void* const* d_in, const int* in_sizes, int n_in,
                              void* d_out, int out_size)
{
    const float* k = (const float*)d_in[0];
    float* out = (float*)d_out;

    const int total_elems = in_sizes[0];
    const int rows = total_elems / ORDER;

    if (rows % RPB == 0) {
        cudaFuncSetAttribute(parcor_to_lpc_bulk,
                             cudaFuncAttributeMaxDynamicSharedMemorySize, TILE_BYTES);
        parcor_to_lpc_bulk<<<rows / RPB, RPB, TILE_BYTES>>>(k, out);
    } else {
        parcor_to_lpc_scalar<<<(rows + 255) / 256, 256>>>(k, out, rows);
    }
}